// round 15
// baseline (speedup 1.0000x reference)
#include <cuda_runtime.h>
#include <cuda_bf16.h>
#include <cstdint>

// Problem constants
#define N0    200000
#define N1    50000
#define N2C   10000
#define INF   602
#define HID   128
#define CLS   41
#define CLSP  44
#define FAN   25

#define KSTEPS 38     // k16 chunks: 38*16 = 608 >= 602
#define NSTAGE 19     // K32 stages
#define W2ROWS 48     // padded class rows (6 * n8)

// Device scratch
__device__ __align__(16) float g_G[N1 * CLSP];
// W1 pre-converted, chunk-major, hi/lo interleaved per frag-uint4: [38][128][16] u32
__device__ __align__(16) uint32_t g_W1k[KSTEPS * HID * 16];
// W2 same packing: [8][48][16] u32
__device__ __align__(16) uint32_t g_W2k[8 * W2ROWS * 16];

// ---- dynamic smem layout for k_layer1 (byte offsets) ----
// phase 1: A ring [2 buf][2 chunk][128][16] u32 = 32768 B; B ring [3][2][128][16] = 49152 B
#define A_OFF    0
#define B_OFF    32768                    // ..81919
// phase 2 (temporally disjoint): H1 [8][128][16] u32 = 65536 B; W2 [8][48][16] = 24576 B
#define H1_OFF   0
#define W2_OFF   65536                    // ..90111
#define SMEM_L1  90112

// ---------------------------------------------------------------------------
// helpers
// ---------------------------------------------------------------------------
__device__ __forceinline__ void mma_bf16(float c[4],
                                         uint32_t a0, uint32_t a1, uint32_t a2, uint32_t a3,
                                         uint32_t b0, uint32_t b1)
{
    asm volatile(
        "mma.sync.aligned.m16n8k16.row.col.f32.bf16.bf16.f32 "
        "{%0,%1,%2,%3}, {%4,%5,%6,%7}, {%8,%9}, {%0,%1,%2,%3};\n"
        : "+f"(c[0]), "+f"(c[1]), "+f"(c[2]), "+f"(c[3])
        : "r"(a0), "r"(a1), "r"(a2), "r"(a3), "r"(b0), "r"(b1));
}

__device__ __forceinline__ void split_pair(float x0, float x1,
                                           uint32_t& hi, uint32_t& lo)
{
    __nv_bfloat162 h2 = __floats2bfloat162_rn(x0, x1);
    float2 hf = __bfloat1622float2(h2);
    __nv_bfloat162 l2 = __floats2bfloat162_rn(x0 - hf.x, x1 - hf.y);
    hi = *reinterpret_cast<uint32_t*>(&h2);
    lo = *reinterpret_cast<uint32_t*>(&l2);
}

__device__ __forceinline__ void cp16(uint32_t dst, const void* src) {
    asm volatile("cp.async.cg.shared.global [%0], [%1], 16;\n"
                 :: "r"(dst), "l"(src));
}
#define CP_COMMIT() asm volatile("cp.async.commit_group;\n" ::: "memory")
#define CP_WAIT(n)  asm volatile("cp.async.wait_group %0;\n" :: "n"(n) : "memory")

// pair i (k = 16p + 2i) -> fragment position c (validated R6-R10)
__device__ __forceinline__ int perm8(int i) {
    return (i < 4) ? (2 * i) : (2 * (i - 4) + 1);
}

// ---------------------------------------------------------------------------
// Kernel 0: W1 / W2 -> bf16 hi/lo, chunk-major, frag-uint4 interleaved.
// Pair i: h at u32 slot 2*perm8(i), l at +1.  uint4 read at 4*i4 then yields
// (h[i4], l[i4], h[i4+4], l[i4+4]) = (b0h, b0l, b1h, b1l).
// ---------------------------------------------------------------------------
#define PREP_W1 (KSTEPS * HID * 8)     // 38912 pairs
#define PREP_W2 (8 * W2ROWS * 8)       // 3072 pairs
__global__ __launch_bounds__(256) void k_prep(const float* __restrict__ W1,
                                              const float* __restrict__ W2)
{
    int idx = blockIdx.x * 256 + threadIdx.x;
    if (idx < PREP_W1) {
        const int p   = idx >> 10;
        const int rem = idx & 1023;
        const int r   = rem >> 3;
        const int i   = rem & 7;
        const int n   = 2 * perm8(i);
        const int k0  = p * 16 + 2 * i;
        float x0 = (k0     < INF) ? W1[(size_t)r * INF + k0]     : 0.f;
        float x1 = (k0 + 1 < INF) ? W1[(size_t)r * INF + k0 + 1] : 0.f;
        uint32_t h, l;
        split_pair(x0, x1, h, l);
        const int base = (p * HID + r) * 16;
        g_W1k[base + n]     = h;
        g_W1k[base + n + 1] = l;
    } else if (idx < PREP_W1 + PREP_W2) {
        const int j   = idx - PREP_W1;
        const int p   = j / 384;
        const int rem = j % 384;
        const int r   = rem >> 3;
        const int i   = rem & 7;
        const int n   = 2 * perm8(i);
        const int k0  = p * 16 + 2 * i;
        float x0 = (r < CLS) ? W2[(size_t)r * HID + k0]     : 0.f;
        float x1 = (r < CLS) ? W2[(size_t)r * HID + k0 + 1] : 0.f;
        uint32_t h, l;
        split_pair(x0, x1, h, l);
        const int base = (p * W2ROWS + r) * 16;
        g_W2k[base + n]     = h;
        g_W2k[base + n + 1] = l;
    }
}

// ---------------------------------------------------------------------------
// Kernel 1 (fused): phase 1: H1 = relu(features[map1] @ W1^T + b1)
//                   phase 2: G = H1 @ W2^T -> g_G
// K32 stages, hi/lo-interleaved smem (LDS.128 frags), cp.async B ring (3 deep).
// ---------------------------------------------------------------------------
__global__ __launch_bounds__(256, 2) void k_layer1(
    const float* __restrict__ features,
    const float* __restrict__ b1,
    const int* __restrict__ map1)
{
    extern __shared__ char smem[];
    const uint32_t sbase = (uint32_t)__cvta_generic_to_shared(smem);
    uint32_t* As = (uint32_t*)(smem + A_OFF);
    const uint32_t* Bs = (const uint32_t*)(smem + B_OFF);
    uint32_t* H1s = (uint32_t*)(smem + H1_OFF);
    const uint32_t* W2s = (const uint32_t*)(smem + W2_OFF);

    const int tid  = threadIdx.x;
    const int warp = tid >> 5;
    const int lane = tid & 31;
    const int g    = lane >> 2;
    const int i4   = lane & 3;
    const int q    = lane >> 3;        // staging row group
    const int o    = lane & 7;         // staging pair
    const int asl  = 2 * perm8(o);     // u32 slot for this pair's (h,l)

    const int row0 = blockIdx.x * 128;

    // 4 staged rows per thread: R_j = warp*16 + 4j + q
    const float* aptr[4];
    bool rv[4];
    int  Rl[4];
    #pragma unroll
    for (int j = 0; j < 4; j++) {
        const int R  = warp * 16 + 4 * j + q;
        const int gr = row0 + R;
        Rl[j] = R;
        rv[j] = (gr < N1);
        const int src = rv[j] ? map1[gr] : 0;
        aptr[j] = features + (size_t)src * INF + 2 * o;   // pair offset baked in
    }

    float2 cur[2][4];
    auto ldA = [&](int s) {
        #pragma unroll
        for (int u = 0; u < 2; u++) {
            const int kb = 32 * s + 16 * u;        // FIXED: aptr already has +2*o
            const bool kv = (kb + 2 * o + 1) < INF;
            #pragma unroll
            for (int j = 0; j < 4; j++)
                cur[u][j] = (rv[j] && kv) ? *(const float2*)(aptr[j] + kb)
                                          : make_float2(0.f, 0.f);
        }
    };

    auto issueB = [&](int p) {     // stage p: 16KB contiguous slab
        const int slot = p % 3;
        #pragma unroll
        for (int jj = 0; jj < 4; jj++)
            cp16(sbase + B_OFF + slot * 16384 + tid * 64 + jj * 16,
                 g_W1k + (size_t)p * 4096 + tid * 16 + jj * 4);
        CP_COMMIT();
    };

    ldA(0);
    issueB(0);
    issueB(1);

    float acc[2][8][4];
    #pragma unroll
    for (int mg = 0; mg < 2; mg++)
        #pragma unroll
        for (int nt = 0; nt < 8; nt++)
            #pragma unroll
            for (int j = 0; j < 4; j++) acc[mg][nt][j] = 0.f;

    const int rowblk = (warp & 3) * 32;
    const int colblk = (warp >> 2) * 64;

    #pragma unroll 1
    for (int s = 0; s < NSTAGE; s++) {
        // convert stage s (both chunks) into buf s&1
        uint32_t* ab = As + (s & 1) * 4096;
        #pragma unroll
        for (int u = 0; u < 2; u++)
            #pragma unroll
            for (int j = 0; j < 4; j++) {
                uint32_t h, l;
                split_pair(cur[u][j].x, cur[u][j].y, h, l);
                *(uint2*)&ab[u * 2048 + Rl[j] * 16 + asl] = make_uint2(h, l);
            }
        if (s + 1 < NSTAGE) ldA(s + 1);

        if (s + 1 < NSTAGE) { CP_WAIT(1); } else { CP_WAIT(0); }
        __syncthreads();
        if (s + 2 < NSTAGE) issueB(s + 2);

        const uint32_t* bb = Bs + (s % 3) * 4096;
        #pragma unroll
        for (int u = 0; u < 2; u++) {
            const uint32_t* au = ab + u * 2048;
            const uint32_t* bu = bb + u * 2048;
            uint4 A0[2], A1[2];
            #pragma unroll
            for (int mg = 0; mg < 2; mg++) {
                const int r = rowblk + mg * 16 + g;
                A0[mg] = *(const uint4*)&au[r * 16 + 4 * i4];
                A1[mg] = *(const uint4*)&au[(r + 8) * 16 + 4 * i4];
            }
            #pragma unroll
            for (int nt = 0; nt < 8; nt++) {
                uint4 bv = *(const uint4*)&bu[(colblk + nt * 8 + g) * 16 + 4 * i4];
                #pragma unroll
                for (int mg = 0; mg < 2; mg++) {
                    mma_bf16(acc[mg][nt], A0[mg].x, A1[mg].x, A0[mg].z, A1[mg].z, bv.x, bv.z);
                    mma_bf16(acc[mg][nt], A0[mg].x, A1[mg].x, A0[mg].z, A1[mg].z, bv.y, bv.w);
                    mma_bf16(acc[mg][nt], A0[mg].y, A1[mg].y, A0[mg].w, A1[mg].w, bv.x, bv.z);
                }
            }
        }
    }

    // ---- phase-1 epilogue: bias + relu, store H1 tile (frag-interleaved) ----
    __syncthreads();   // all phase-1 smem reads done before overwrite
    #pragma unroll
    for (int mg = 0; mg < 2; mg++) {
        const int r0 = rowblk + mg * 16 + g;
        const int r1 = r0 + 8;
        #pragma unroll
        for (int nt = 0; nt < 8; nt++) {
            const int col = colblk + nt * 8 + 2 * i4;
            const int kc  = col >> 4;
            const int ii  = (col & 15) >> 1;
            const int sl  = 2 * perm8(ii);
            const float bb0 = b1[col], bb1 = b1[col + 1];
            {
                float v0 = acc[mg][nt][0] + bb0; v0 = v0 > 0.f ? v0 : 0.f;
                float v1 = acc[mg][nt][1] + bb1; v1 = v1 > 0.f ? v1 : 0.f;
                uint32_t h, l;
                split_pair(v0, v1, h, l);
                *(uint2*)&H1s[(kc * 128 + r0) * 16 + sl] = make_uint2(h, l);
            }
            {
                float v0 = acc[mg][nt][2] + bb0; v0 = v0 > 0.f ? v0 : 0.f;
                float v1 = acc[mg][nt][3] + bb1; v1 = v1 > 0.f ? v1 : 0.f;
                uint32_t h, l;
                split_pair(v0, v1, h, l);
                *(uint2*)&H1s[(kc * 128 + r1) * 16 + sl] = make_uint2(h, l);
            }
        }
    }
    // load W2 slabs into smem (region dead since last B-ring use)
    {
        uint4* dst = (uint4*)(smem + W2_OFF);
        const uint4* src = (const uint4*)g_W2k;
        for (int i = tid; i < (8 * W2ROWS * 16) / 4; i += 256)
            dst[i] = src[i];
    }
    __syncthreads();

    // ---- phase 2: G tile = H1 tile @ W2^T ----
    float gacc[6][4];
    #pragma unroll
    for (int t = 0; t < 6; t++)
        #pragma unroll
        for (int j = 0; j < 4; j++) gacc[t][j] = 0.f;

    const int r2 = warp * 16 + g;

    #pragma unroll
    for (int kc = 0; kc < 8; kc++) {
        uint4 A0 = *(const uint4*)&H1s[(kc * 128 + r2) * 16 + 4 * i4];
        uint4 A1 = *(const uint4*)&H1s[(kc * 128 + r2 + 8) * 16 + 4 * i4];
        #pragma unroll
        for (int nt = 0; nt < 6; nt++) {
            uint4 bv = *(const uint4*)&W2s[(kc * W2ROWS + nt * 8 + g) * 16 + 4 * i4];
            mma_bf16(gacc[nt], A0.x, A1.x, A0.z, A1.z, bv.x, bv.z);
            mma_bf16(gacc[nt], A0.x, A1.x, A0.z, A1.z, bv.y, bv.w);
            mma_bf16(gacc[nt], A0.y, A1.y, A0.w, A1.w, bv.x, bv.z);
        }
    }

    // ---- phase-2 epilogue -> g_G ----
    const int r0g = row0 + r2;
    const int r1g = r0g + 8;
    #pragma unroll
    for (int nt = 0; nt < 6; nt++) {
        const int col = nt * 8 + 2 * i4;
        if (col + 1 < CLSP) {
            if (r0g < N1)
                *(float2*)(&g_G[(size_t)r0g * CLSP + col]) =
                    make_float2(gacc[nt][0], gacc[nt][1]);
            if (r1g < N1)
                *(float2*)(&g_G[(size_t)r1g * CLSP + col]) =
                    make_float2(gacc[nt][2], gacc[nt][3]);
        }
    }
}

// ---------------------------------------------------------------------------
// Kernel 2: out[n][c] = b2[c] + mean_j G[neigh[n][j]][c]
// One warp per seed; lanes 0..10 hold the 44-col row as float4.
// ---------------------------------------------------------------------------
__global__ __launch_bounds__(256) void k_gather(
    const int* __restrict__ neigh,
    const float* __restrict__ b2,
    float* __restrict__ out)
{
    const int warp = threadIdx.x >> 5;
    const int lane = threadIdx.x & 31;
    const int n    = blockIdx.x * 8 + warp;

    const int nbv = (lane < FAN) ? neigh[(size_t)n * FAN + lane] : 0;

    float4 a4 = make_float4(0.f, 0.f, 0.f, 0.f);
    const float4* G4 = (const float4*)g_G;
    #pragma unroll
    for (int j = 0; j < FAN; j++) {
        const int idx = __shfl_sync(0xffffffffu, nbv, j);
        if (lane < 11) {
            float4 v = G4[(size_t)idx * 11 + lane];
            a4.x += v.x; a4.y += v.y; a4.z += v.z; a4.w += v.w;
        }
    }
    if (lane < 11) {
        const float inv = 1.0f / FAN;
        float vals[4] = {a4.x, a4.y, a4.z, a4.w};
        #pragma unroll
        for (int e = 0; e < 4; e++) {
            const int c = lane * 4 + e;
            if (c < CLS)
                out[(size_t)n * CLS + c] = fmaf(vals[e], inv, b2[c]);
        }
    }
}

// ---------------------------------------------------------------------------
// Launch.  Inputs: features f32, W1 f32, b1 f32, W2 f32, b2 f32,
//                  map1 i32, neigh_idx i32.  Output: f32 [N2*CLS].
// ---------------------------------------------------------------------------
extern "C" void kernel_launch(void* const* d_in, const int* in_sizes, int n_in,
                              void* d_out, int out_size) {
    const float* features = (const float*)d_in[0];
    const float* W1       = (const float*)d_in[1];
    const float* b1       = (const float*)d_in[2];
    const float* W2       = (const float*)d_in[3];
    const float* b2       = (const float*)d_in[4];
    const int*   map1     = (const int*)d_in[5];
    const int*   neigh    = (const int*)d_in[6];
    float*       out      = (float*)d_out;

    static bool attr_done = false;
    if (!attr_done) {
        cudaFuncSetAttribute(k_layer1,
                             cudaFuncAttributeMaxDynamicSharedMemorySize, SMEM_L1);
        attr_done = true;
    }

    const int gridp = (PREP_W1 + PREP_W2 + 255) / 256;   // 164
    k_prep<<<gridp, 256>>>(W1, W2);

    const int grid1 = (N1 + 127) / 128;                  // 391
    k_layer1<<<grid1, 256, SMEM_L1>>>(features, b1, map1);

    k_gather<<<N2C / 8, 256>>>(neigh, b2, out);          // 1250 blocks
}